// round 4
// baseline (speedup 1.0000x reference)
#include <cuda_runtime.h>
#include <cuda_bf16.h>
#include <cstdint>

#define BB 4
#define TT 4096
#define EE 2048
#define DD 128
#define KTOP 409
#define NBAND 16   // refinement band: ranks [KTOP-8, KTOP+8)

// ---------------- scratch (device globals) ----------------
__device__ float g_q[(size_t)BB * TT * DD];
__device__ float g_norm[BB * TT];
__device__ int   g_topidx[BB * KTOP];
__device__ int   g_band[BB][NBAND];
__device__ float g_bnorm[BB][NBAND];
__device__ float g_qtop[BB * KTOP * DD];
__device__ float g_ktop[BB * KTOP * DD];
__device__ float g_vtop[BB * KTOP * DD];
// W transposed + split into 2 bf16 limbs: [mat][limb][n(128)][k(2048)]
__device__ __nv_bfloat16 g_wt[3][2][DD][EE];

// ---------------- helpers ----------------
__device__ __forceinline__ uint32_t smem_u32(const void* p) {
    uint32_t a;
    asm("{ .reg .u64 t; cvta.to.shared.u64 t, %1; cvt.u32.u64 %0, t; }"
        : "=r"(a) : "l"(p));
    return a;
}
__device__ __forceinline__ void ldsm4(uint32_t* r, uint32_t addr) {
    asm volatile("ldmatrix.sync.aligned.m8n8.x4.shared.b16 {%0,%1,%2,%3}, [%4];"
                 : "=r"(r[0]), "=r"(r[1]), "=r"(r[2]), "=r"(r[3]) : "r"(addr));
}
__device__ __forceinline__ void mma16816(float* c, const uint32_t* a,
                                         const uint32_t* b) {
    asm volatile(
        "mma.sync.aligned.m16n8k16.row.col.f32.bf16.bf16.f32 "
        "{%0,%1,%2,%3}, {%4,%5,%6,%7}, {%8,%9}, {%0,%1,%2,%3};"
        : "+f"(c[0]), "+f"(c[1]), "+f"(c[2]), "+f"(c[3])
        : "r"(a[0]), "r"(a[1]), "r"(a[2]), "r"(a[3]), "r"(b[0]), "r"(b[1]));
}
__device__ __forceinline__ void sts64(uint32_t a, uint32_t lo, uint32_t hi) {
    asm volatile("st.shared.v2.b32 [%0], {%1,%2};" :: "r"(a), "r"(lo), "r"(hi));
}
__device__ __forceinline__ void sts128(uint32_t a, uint4 v) {
    asm volatile("st.shared.v4.b32 [%0], {%1,%2,%3,%4};"
                 :: "r"(a), "r"(v.x), "r"(v.y), "r"(v.z), "r"(v.w));
}
__device__ __forceinline__ uint32_t pack_bf16x2(__nv_bfloat162 v) {
    return *reinterpret_cast<uint32_t*>(&v);
}

// ---------------- geometry ----------------
constexpr int BK = 32;            // k elems per chunk
constexpr int NCH = EE / BK;      // 64
constexpr int LDAB = 80;          // smem row stride in bytes (40 bf16)
constexpr int AB = 128 * LDAB;    // 10240 bytes per limb-buffer
constexpr uint32_t S_W = 4 * AB;  // W limbs after A limbs
constexpr uint32_t S_TOTAL = 8 * AB;  // 81920

// ---------------- zero output ----------------
__global__ void zero_kernel(float4* o, int n4) {
    for (int i = blockIdx.x * blockDim.x + threadIdx.x; i < n4;
         i += gridDim.x * blockDim.x)
        o[i] = make_float4(0.f, 0.f, 0.f, 0.f);
}

// ---------------- W prep: transpose + 2-limb bf16 split ----------------
__global__ void wprep_kernel(const float* __restrict__ Wq,
                             const float* __restrict__ Wk,
                             const float* __restrict__ Wv) {
    __shared__ float t[32][33];
    const int tid = threadIdx.x;
    const int bk = blockIdx.x * 32, bn = blockIdx.y * 32;
    const float* Ws[3] = {Wq, Wk, Wv};
    for (int m = 0; m < 3; m++) {
        const float* W = Ws[m];
#pragma unroll
        for (int p = 0; p < 4; p++) {
            int i = p * 8 + (tid >> 5), j = tid & 31;
            t[i][j] = W[(bk + i) * DD + bn + j];
        }
        __syncthreads();
#pragma unroll
        for (int p = 0; p < 4; p++) {
            int j = p * 8 + (tid >> 5), i = tid & 31;
            float x = t[i][j];
            __nv_bfloat16 h = __float2bfloat16_rn(x);
            float r1 = x - __bfloat162float(h);
            __nv_bfloat16 md = __float2bfloat16_rn(r1);
            int n = bn + j, k = bk + i;
            g_wt[m][0][n][k] = h;
            g_wt[m][1][n][k] = md;
        }
        __syncthreads();
    }
}

// ---------------- mma.sync split-bf16 GEMM ----------------
// D[128,128] = A_tile[128,2048] @ W[2048,128], ~fp32-accurate (3 limb pairs).
// !GATHER: grid=128 row tiles -> g_q + g_norm.  GATHER: grid=(16,2) -> g_ktop/g_vtop.
template <bool GATHER>
__global__ __launch_bounds__(256, 1) void gemm_mma(const float* __restrict__ A) {
    extern __shared__ char smem[];
    __shared__ float npart[2][128];
    const uint32_t sb = smem_u32(smem);
    const int tid = threadIdx.x, wid = tid >> 5, lane = tid & 31;
    const int wr = wid >> 1, wc = wid & 1;   // 4 row-warps x 2 col-warps
    const int row0 = wr * 32, n0 = wc * 64;

    int b = 0, tile, mat = 0;
    const __nv_bfloat16* wt;
    if (GATHER) {
        b = blockIdx.x >> 2;
        tile = blockIdx.x & 3;
        mat = blockIdx.y;
        wt = &g_wt[1 + mat][0][0][0];
    } else {
        tile = blockIdx.x;
        wt = &g_wt[0][0][0][0];
    }

    // -------- per-thread gmem pointers + smem store offsets --------
    const float* aptr[4];
    uint32_t asm_[4];
#pragma unroll
    for (int i = 0; i < 4; i++) {
        int idx = tid + 256 * i;          // 0..1023
        int r = idx >> 3, kc = (idx & 7) * 4;
        if (GATHER) {
            int rl = tile * 128 + r;
            if (rl >= KTOP) rl = KTOP - 1;
            int gr = g_topidx[b * KTOP + rl];
            aptr[i] = A + ((size_t)b * TT + gr) * EE + kc;
        } else {
            aptr[i] = A + (size_t)(tile * 128 + r) * EE + kc;
        }
        asm_[i] = r * LDAB + kc * 2;
    }
    const __nv_bfloat16* wptr[4];
    uint32_t wsm[4];
#pragma unroll
    for (int j = 0; j < 4; j++) {
        int idx = tid + 256 * j;          // 0..1023
        int limb = idx >> 9, rem = idx & 511;
        int n = rem >> 2, kq = (rem & 3) * 8;
        wptr[j] = wt + (size_t)limb * DD * EE + (size_t)n * EE + kq;
        wsm[j] = limb * AB + n * LDAB + kq * 2;
    }

    // -------- ldmatrix lane offsets --------
    uint32_t aoff[2], boff[4];
#pragma unroll
    for (int mt = 0; mt < 2; mt++)
        aoff[mt] = (row0 + mt * 16 + (lane & 15)) * LDAB + (lane >> 4) * 16;
#pragma unroll
    for (int np = 0; np < 4; np++) {
        int nl = n0 + np * 16 + (lane & 7) + ((lane >> 4) & 1) * 8;
        boff[np] = nl * LDAB + (lane & 8) * 2;
    }

    float c[2][8][4];
#pragma unroll
    for (int mt = 0; mt < 2; mt++)
#pragma unroll
        for (int nt = 0; nt < 8; nt++)
#pragma unroll
            for (int u = 0; u < 4; u++) c[mt][nt][u] = 0.f;

    float4 av[4];
    uint4 wv[4];

    // load chunk 0
#pragma unroll
    for (int i = 0; i < 4; i++) av[i] = *(const float4*)(aptr[i]);
#pragma unroll
    for (int j = 0; j < 4; j++) wv[j] = *(const uint4*)(wptr[j]);

    // store chunk 0 into buffer 0
    {
        const uint32_t abase = sb, wbase = sb + S_W;
#pragma unroll
        for (int i = 0; i < 4; i++) {
            __nv_bfloat162 h0 = __float22bfloat162_rn(make_float2(av[i].x, av[i].y));
            __nv_bfloat162 h1 = __float22bfloat162_rn(make_float2(av[i].z, av[i].w));
            float2 hf0 = __bfloat1622float2(h0), hf1 = __bfloat1622float2(h1);
            __nv_bfloat162 m0 = __float22bfloat162_rn(
                make_float2(av[i].x - hf0.x, av[i].y - hf0.y));
            __nv_bfloat162 m1 = __float22bfloat162_rn(
                make_float2(av[i].z - hf1.x, av[i].w - hf1.y));
            sts64(abase + asm_[i], pack_bf16x2(h0), pack_bf16x2(h1));
            sts64(abase + AB + asm_[i], pack_bf16x2(m0), pack_bf16x2(m1));
        }
#pragma unroll
        for (int j = 0; j < 4; j++) sts128(wbase + wsm[j], wv[j]);
    }
    __syncthreads();

    for (int it = 0; it < NCH; ++it) {
        const int buf = it & 1;
        if (it + 1 < NCH) {
            const int kb = (it + 1) * BK;
#pragma unroll
            for (int i = 0; i < 4; i++) av[i] = *(const float4*)(aptr[i] + kb);
#pragma unroll
            for (int j = 0; j < 4; j++) wv[j] = *(const uint4*)(wptr[j] + kb);
        }

        // ---- compute chunk `it` from buffer `buf` ----
        const uint32_t aH = sb + buf * 2 * AB;
        const uint32_t aM = aH + AB;
        const uint32_t wH = sb + S_W + buf * 2 * AB;
        const uint32_t wM = wH + AB;
#pragma unroll
        for (int kk = 0; kk < 2; kk++) {
            uint32_t ah[2][4], am[2][4], bh[4][4], bm[4][4];
#pragma unroll
            for (int mt = 0; mt < 2; mt++) {
                ldsm4(ah[mt], aH + aoff[mt] + kk * 32);
                ldsm4(am[mt], aM + aoff[mt] + kk * 32);
            }
#pragma unroll
            for (int np = 0; np < 4; np++) {
                ldsm4(bh[np], wH + boff[np] + kk * 32);
                ldsm4(bm[np], wM + boff[np] + kk * 32);
            }
#pragma unroll
            for (int mt = 0; mt < 2; mt++)
#pragma unroll
                for (int nt = 0; nt < 8; nt++) {
                    const uint32_t* BH = &bh[nt >> 1][(nt & 1) * 2];
                    const uint32_t* BM = &bm[nt >> 1][(nt & 1) * 2];
                    mma16816(c[mt][nt], ah[mt], BH);
                    mma16816(c[mt][nt], ah[mt], BM);
                    mma16816(c[mt][nt], am[mt], BH);
                }
        }

        if (it + 1 < NCH) {
            __syncthreads();
            const uint32_t abase = sb + ((it + 1) & 1) * 2 * AB;
            const uint32_t wbase = sb + S_W + ((it + 1) & 1) * 2 * AB;
#pragma unroll
            for (int i = 0; i < 4; i++) {
                __nv_bfloat162 h0 =
                    __float22bfloat162_rn(make_float2(av[i].x, av[i].y));
                __nv_bfloat162 h1 =
                    __float22bfloat162_rn(make_float2(av[i].z, av[i].w));
                float2 hf0 = __bfloat1622float2(h0), hf1 = __bfloat1622float2(h1);
                __nv_bfloat162 m0 = __float22bfloat162_rn(
                    make_float2(av[i].x - hf0.x, av[i].y - hf0.y));
                __nv_bfloat162 m1 = __float22bfloat162_rn(
                    make_float2(av[i].z - hf1.x, av[i].w - hf1.y));
                sts64(abase + asm_[i], pack_bf16x2(h0), pack_bf16x2(h1));
                sts64(abase + AB + asm_[i], pack_bf16x2(m0), pack_bf16x2(m1));
            }
#pragma unroll
            for (int j = 0; j < 4; j++) sts128(wbase + wsm[j], wv[j]);
            __syncthreads();
        }
    }

    // -------- epilogue --------
    if (!GATHER) {
#pragma unroll
        for (int mt = 0; mt < 2; mt++) {
            float slo = 0.f, shi = 0.f;
#pragma unroll
            for (int nt = 0; nt < 8; nt++) {
                slo += c[mt][nt][0] * c[mt][nt][0] + c[mt][nt][1] * c[mt][nt][1];
                shi += c[mt][nt][2] * c[mt][nt][2] + c[mt][nt][3] * c[mt][nt][3];
            }
            slo += __shfl_xor_sync(0xffffffffu, slo, 1);
            slo += __shfl_xor_sync(0xffffffffu, slo, 2);
            shi += __shfl_xor_sync(0xffffffffu, shi, 1);
            shi += __shfl_xor_sync(0xffffffffu, shi, 2);
            if ((lane & 3) == 0) {
                int rl = row0 + mt * 16 + (lane >> 2);
                npart[wc][rl] = slo;
                npart[wc][rl + 8] = shi;
            }
        }
        __syncthreads();
        if (tid < 128)
            g_norm[tile * 128 + tid] = npart[0][tid] + npart[1][tid];
    }

#pragma unroll
    for (int mt = 0; mt < 2; mt++) {
        int rl = row0 + mt * 16 + (lane >> 2);
#pragma unroll
        for (int nt = 0; nt < 8; nt++) {
            int col = n0 + nt * 8 + (lane & 3) * 2;
            if (!GATHER) {
                float* p0 = g_q + (size_t)(tile * 128 + rl) * DD + col;
                *(float2*)p0 = make_float2(c[mt][nt][0], c[mt][nt][1]);
                *(float2*)(p0 + 8 * DD) = make_float2(c[mt][nt][2], c[mt][nt][3]);
            } else {
                int r0g = tile * 128 + rl;
                float* base = (mat ? g_vtop : g_ktop);
                if (r0g < KTOP) {
                    float* p0 = base + ((size_t)b * KTOP + r0g) * DD + col;
                    *(float2*)p0 = make_float2(c[mt][nt][0], c[mt][nt][1]);
                }
                if (r0g + 8 < KTOP) {
                    float* p1 = base + ((size_t)b * KTOP + r0g + 8) * DD + col;
                    *(float2*)p1 = make_float2(c[mt][nt][2], c[mt][nt][3]);
                }
            }
        }
    }
}

// ---------------- per-batch sort of norms (bitonic, tie-break lower index) ----
__global__ __launch_bounds__(1024) void sort_kernel() {
    __shared__ unsigned long long key[TT];
    const int b = blockIdx.x, tid = threadIdx.x;
    for (int t = tid; t < TT; t += 1024) {
        unsigned bits = __float_as_uint(g_norm[b * TT + t]);
        key[t] = ((unsigned long long)bits << 32) | (unsigned)(0xFFFFFFFFu - t);
    }
    __syncthreads();
    for (int k = 2; k <= TT; k <<= 1) {
        for (int j = k >> 1; j > 0; j >>= 1) {
            for (int t = tid; t < TT; t += 1024) {
                int l = t ^ j;
                if (l > t) {
                    unsigned long long a = key[t], c = key[l];
                    bool up = ((t & k) == 0);
                    if ((a > c) == up) {
                        key[t] = c;
                        key[l] = a;
                    }
                }
            }
            __syncthreads();
        }
    }
    if (tid < KTOP + 8) {
        unsigned long long kk = key[TT - 1 - tid];
        int idx = (int)(0xFFFFFFFFu - (unsigned)(kk & 0xFFFFFFFFull));
        if (tid < KTOP - 8) g_topidx[b * KTOP + tid] = idx;
        else g_band[b][tid - (KTOP - 8)] = idx;
    }
}

// ---------------- exact fp32 norms for band rows ----------------
__global__ __launch_bounds__(128) void refine_kernel(const float* __restrict__ A,
                                                     const float* __restrict__ Wq) {
    const int slot = blockIdx.x, b = blockIdx.y;
    const int n = threadIdx.x;
    const int row = g_band[b][slot];
    const float* x = A + ((size_t)b * TT + row) * EE;
    float s0 = 0.f, s1 = 0.f, s2 = 0.f, s3 = 0.f;
#pragma unroll 4
    for (int k = 0; k < EE; k += 4) {
        float x0 = __ldg(x + k), x1 = __ldg(x + k + 1);
        float x2 = __ldg(x + k + 2), x3 = __ldg(x + k + 3);
        s0 += x0 * __ldg(Wq + (size_t)k * DD + n);
        s1 += x1 * __ldg(Wq + (size_t)(k + 1) * DD + n);
        s2 += x2 * __ldg(Wq + (size_t)(k + 2) * DD + n);
        s3 += x3 * __ldg(Wq + (size_t)(k + 3) * DD + n);
    }
    float q = (s0 + s1) + (s2 + s3);
    __shared__ float red[128];
    red[n] = q * q;
    __syncthreads();
    for (int o = 64; o > 0; o >>= 1) {
        if (n < o) red[n] += red[n + o];
        __syncthreads();
    }
    if (n == 0) g_bnorm[b][slot] = red[0];
}

// ---------------- finalize selection + gather q_top ----------------
__global__ __launch_bounds__(1024) void finalize_kernel() {
    const int b = blockIdx.x, tid = threadIdx.x;
    __shared__ int sidx[KTOP];
    __shared__ unsigned long long bkey[NBAND];
    if (tid < NBAND) {
        int r = g_band[b][tid];
        unsigned nb = __float_as_uint(g_bnorm[b][tid]);
        bkey[tid] = ((unsigned long long)nb << 32) | (unsigned)(0xFFFFFFFFu - r);
    }
    __syncthreads();
    if (tid < NBAND) {
        unsigned long long me = bkey[tid];
        int rank = 0;
#pragma unroll
        for (int t = 0; t < NBAND; t++) rank += (bkey[t] > me);
        if (rank < 8) {
            int r = (int)(0xFFFFFFFFu - (unsigned)(me & 0xFFFFFFFFull));
            g_topidx[b * KTOP + (KTOP - 8) + rank] = r;
            sidx[(KTOP - 8) + rank] = r;
        }
    }
    for (int t = tid; t < KTOP - 8; t += 1024) sidx[t] = g_topidx[b * KTOP + t];
    __syncthreads();
    for (int u = tid; u < KTOP * DD; u += 1024) {
        int r = u >> 7, d = u & 127;
        g_qtop[((size_t)b * KTOP + r) * DD + d] =
            g_q[((size_t)b * TT + sidx[r]) * DD + d];
    }
}

// ---------------- attention on the top-k set, scattered store ----------------
__global__ __launch_bounds__(256) void attn_kernel(float* __restrict__ out) {
    constexpr int QT = 16;
    constexpr int NT = 26;
    constexpr int CW = 416;
    __shared__ float q_s[QT][132];
    __shared__ float kv_s[QT][132];
    __shared__ float S_s[QT][CW];

    const int b = blockIdx.x / NT;
    const int qt = blockIdx.x % NT;
    const int q0 = qt * QT;
    const int tid = threadIdx.x;
    const float scale = 0.08838834764831845f;

    for (int u = tid; u < QT * DD; u += 256) {
        int i = u >> 7, d = u & 127;
        int r = q0 + i;
        q_s[i][d] = (r < KTOP) ? g_qtop[((size_t)b * KTOP + r) * DD + d] : 0.f;
    }

    const int i = tid >> 4;
    const int jj = tid & 15;

    for (int jt = 0; jt < NT; jt++) {
        __syncthreads();
        for (int u = tid; u < QT * DD; u += 256) {
            int j2 = u >> 7, d = u & 127;
            int j = jt * QT + j2;
            kv_s[j2][d] = (j < KTOP) ? g_ktop[((size_t)b * KTOP + j) * DD + d] : 0.f;
        }
        __syncthreads();
        float s = 0.f;
#pragma unroll
        for (int d4 = 0; d4 < DD; d4 += 4) {
            float4 qa = *(const float4*)&q_s[i][d4];
            float4 kb = *(const float4*)&kv_s[jj][d4];
            s += qa.x * kb.x + qa.y * kb.y + qa.z * kb.z + qa.w * kb.w;
        }
        int j = jt * QT + jj;
        S_s[i][j] = (j < KTOP) ? s * scale : -1e30f;
    }
    __syncthreads();

    {
        int l = tid & 15;
        float m = -1e30f;
        for (int cc = l; cc < CW; cc += 16) m = fmaxf(m, S_s[i][cc]);
#pragma unroll
        for (int o = 8; o; o >>= 1) m = fmaxf(m, __shfl_xor_sync(0xffffffffu, m, o));
        float sum = 0.f;
        for (int cc = l; cc < CW; cc += 16) {
            float e = __expf(S_s[i][cc] - m);
            S_s[i][cc] = e;
            sum += e;
        }
#pragma unroll
        for (int o = 8; o; o >>= 1) sum += __shfl_xor_sync(0xffffffffu, sum, o);
        float inv = 1.f / sum;
        for (int cc = l; cc < CW; cc += 16) S_s[i][cc] *= inv;
    }

    float acc[8] = {0.f, 0.f, 0.f, 0.f, 0.f, 0.f, 0.f, 0.f};
    const int d0 = (tid & 15) * 8;
    for (int jt = 0; jt < NT; jt++) {
        __syncthreads();
        for (int u = tid; u < QT * DD; u += 256) {
            int j2 = u >> 7, d = u & 127;
            int j = jt * QT + j2;
            kv_s[j2][d] = (j < KTOP) ? g_vtop[((size_t)b * KTOP + j) * DD + d] : 0.f;
        }
        __syncthreads();
#pragma unroll
        for (int j2 = 0; j2 < QT; j2++) {
            float p = S_s[i][jt * QT + j2];
            float4 v0 = *(const float4*)&kv_s[j2][d0];
            float4 v1 = *(const float4*)&kv_s[j2][d0 + 4];
            acc[0] += p * v0.x;
            acc[1] += p * v0.y;
            acc[2] += p * v0.z;
            acc[3] += p * v0.w;
            acc[4] += p * v1.x;
            acc[5] += p * v1.y;
            acc[6] += p * v1.z;
            acc[7] += p * v1.w;
        }
    }
    int r = q0 + i;
    if (r < KTOP) {
        int rg = g_topidx[b * KTOP + r];
        float* op = out + ((size_t)b * TT + rg) * DD + d0;
        *(float4*)op = make_float4(acc[0], acc[1], acc[2], acc[3]);
        *(float4*)(op + 4) = make_float4(acc[4], acc[5], acc[6], acc[7]);
    }
}

// ---------------- launch ----------------
extern "C" void kernel_launch(void* const* d_in, const int* in_sizes, int n_in,
                              void* d_out, int out_size) {
    (void)in_sizes;
    (void)n_in;
    (void)out_size;
    const float* index = (const float*)d_in[0];
    const float* Wq = (const float*)d_in[1];
    const float* Wk = (const float*)d_in[2];
    const float* Wv = (const float*)d_in[3];
    float* out = (float*)d_out;

    cudaFuncSetAttribute(gemm_mma<false>,
                         cudaFuncAttributeMaxDynamicSharedMemorySize, S_TOTAL);
    cudaFuncSetAttribute(gemm_mma<true>,
                         cudaFuncAttributeMaxDynamicSharedMemorySize, S_TOTAL);

    zero_kernel<<<512, 256>>>((float4*)out, BB * TT * DD / 4);
    wprep_kernel<<<dim3(EE / 32, DD / 32), 256>>>(Wq, Wk, Wv);
    gemm_mma<false><<<(BB * TT) / 128, 256, S_TOTAL>>>(index);
    sort_kernel<<<BB, 1024>>>();
    refine_kernel<<<dim3(NBAND, BB), 128>>>(index, Wq);
    finalize_kernel<<<BB, 1024>>>();
    gemm_mma<true><<<dim3(16, 2), 256, S_TOTAL>>>(index);
    attn_kernel<<<BB * 26, 256>>>(out);
}

// round 8
// speedup vs baseline: 1.1253x; 1.1253x over previous
#include <cuda_runtime.h>
#include <cuda_bf16.h>
#include <cstdint>

#define BB 4
#define TT 4096
#define EE 2048
#define DD 128
#define KTOP 409
#define NCAND 32
#define NKV 4   // split-K slices for gather GEMM

// ---------------- scratch (device globals) ----------------
__device__ float g_q[(size_t)BB * TT * DD];
__device__ float g_norm[BB * TT];
__device__ int   g_topidx[BB * KTOP];
__device__ int   g_nsel[BB];
__device__ int   g_ncand[BB];
__device__ int   g_band[BB][NCAND];
__device__ float g_bnorm[BB][NCAND];
__device__ float g_qtop[BB * KTOP * DD];
__device__ float g_ktop[BB * KTOP * DD];
__device__ float g_vtop[BB * KTOP * DD];
__device__ float g_part[(size_t)NKV * 2 * BB * KTOP * DD];
// W transposed + split into 2 bf16 limbs: [mat][limb][n(128)][k(2048)]
__device__ __nv_bfloat16 g_wt[3][2][DD][EE];

// ---------------- helpers ----------------
__device__ __forceinline__ uint32_t smem_u32(const void* p) {
    uint32_t a;
    asm("{ .reg .u64 t; cvta.to.shared.u64 t, %1; cvt.u32.u64 %0, t; }"
        : "=r"(a) : "l"(p));
    return a;
}
__device__ __forceinline__ void ldsm4(uint32_t* r, uint32_t addr) {
    asm volatile("ldmatrix.sync.aligned.m8n8.x4.shared.b16 {%0,%1,%2,%3}, [%4];"
                 : "=r"(r[0]), "=r"(r[1]), "=r"(r[2]), "=r"(r[3]) : "r"(addr));
}
__device__ __forceinline__ void mma16816(float* c, const uint32_t* a,
                                         const uint32_t* b) {
    asm volatile(
        "mma.sync.aligned.m16n8k16.row.col.f32.bf16.bf16.f32 "
        "{%0,%1,%2,%3}, {%4,%5,%6,%7}, {%8,%9}, {%0,%1,%2,%3};"
        : "+f"(c[0]), "+f"(c[1]), "+f"(c[2]), "+f"(c[3])
        : "r"(a[0]), "r"(a[1]), "r"(a[2]), "r"(a[3]), "r"(b[0]), "r"(b[1]));
}
__device__ __forceinline__ void sts64(uint32_t a, uint32_t lo, uint32_t hi) {
    asm volatile("st.shared.v2.b32 [%0], {%1,%2};" :: "r"(a), "r"(lo), "r"(hi));
}
__device__ __forceinline__ void sts128(uint32_t a, uint4 v) {
    asm volatile("st.shared.v4.b32 [%0], {%1,%2,%3,%4};"
                 :: "r"(a), "r"(v.x), "r"(v.y), "r"(v.z), "r"(v.w));
}
__device__ __forceinline__ uint32_t pack_bf16x2(__nv_bfloat162 v) {
    return *reinterpret_cast<uint32_t*>(&v);
}

// ---------------- geometry ----------------
constexpr int BK = 32;
constexpr int NCH = EE / BK;      // 64 chunks (full depth)
constexpr int LDAB = 80;          // smem row stride bytes (conflict-free ldmatrix)
constexpr int AB = 128 * LDAB;    // 10240 bytes per limb buffer
constexpr uint32_t S_W = 4 * AB;
constexpr uint32_t S_TOTAL = 8 * AB;  // 81920 (2 CTAs/SM fit in 228KB)

// ---------------- zero output ----------------
__global__ void zero_kernel(float4* o, int n4) {
    for (int i = blockIdx.x * blockDim.x + threadIdx.x; i < n4;
         i += gridDim.x * blockDim.x)
        o[i] = make_float4(0.f, 0.f, 0.f, 0.f);
}

// ---------------- W prep: transpose + 2-limb bf16 split ----------------
__global__ void wprep_kernel(const float* __restrict__ Wq,
                             const float* __restrict__ Wk,
                             const float* __restrict__ Wv) {
    __shared__ float t[32][33];
    const int tid = threadIdx.x;
    const int bk = blockIdx.x * 32, bn = blockIdx.y * 32;
    const float* Ws[3] = {Wq, Wk, Wv};
    for (int m = 0; m < 3; m++) {
        const float* W = Ws[m];
#pragma unroll
        for (int p = 0; p < 4; p++) {
            int i = p * 8 + (tid >> 5), j = tid & 31;
            t[i][j] = W[(bk + i) * DD + bn + j];
        }
        __syncthreads();
#pragma unroll
        for (int p = 0; p < 4; p++) {
            int j = p * 8 + (tid >> 5), i = tid & 31;
            float x = t[i][j];
            __nv_bfloat16 h = __float2bfloat16_rn(x);
            float r1 = x - __bfloat162float(h);
            __nv_bfloat16 md = __float2bfloat16_rn(r1);
            int n = bn + j, k = bk + i;
            g_wt[m][0][n][k] = h;
            g_wt[m][1][n][k] = md;
        }
        __syncthreads();
    }
}

// ---------------- tiny init (placeholder to keep gemm at launch #4) --------
__global__ void init_sel() {
    if (threadIdx.x < BB) {
        g_nsel[threadIdx.x] = 0;
        g_ncand[threadIdx.x] = 0;
    }
}

// ---------------- mma.sync split-bf16 GEMM ----------------
// !GATHER: grid=128 tiles, full depth -> g_q + g_norm.
// GATHER : grid=(16, 2, NKV) split-K -> g_part slices.
template <bool GATHER>
__global__ __launch_bounds__(256, 2) void gemm_mma(const float* __restrict__ A) {
    extern __shared__ char smem[];
    __shared__ float npart[2][128];
    const uint32_t sb = smem_u32(smem);
    const int tid = threadIdx.x, wid = tid >> 5, lane = tid & 31;
    const int wr = wid >> 1, wc = wid & 1;
    const int row0 = wr * 32, n0 = wc * 64;

    int b = 0, tile, mat = 0, kbase = 0, nch = NCH;
    const __nv_bfloat16* wt;
    float* part = nullptr;
    if (GATHER) {
        b = blockIdx.x >> 2;
        tile = blockIdx.x & 3;
        mat = blockIdx.y;
        kbase = blockIdx.z * (EE / NKV);
        nch = (EE / NKV) / BK;   // 16
        wt = &g_wt[1 + mat][0][0][0];
        part = g_part + (size_t)(blockIdx.z * 2 + mat) * (BB * KTOP * DD);
    } else {
        tile = blockIdx.x;
        wt = &g_wt[0][0][0][0];
    }

    // -------- per-thread gmem offsets + smem store offsets --------
    uint32_t aoffg[4], asm_[4];
#pragma unroll
    for (int i = 0; i < 4; i++) {
        int idx = tid + 256 * i;
        int r = idx >> 3, kc = (idx & 7) * 4;
        int gr;
        if (GATHER) {
            int rl = tile * 128 + r;
            if (rl >= KTOP) rl = KTOP - 1;
            gr = b * TT + g_topidx[b * KTOP + rl];
        } else {
            gr = tile * 128 + r;
        }
        aoffg[i] = (uint32_t)gr * EE + kbase + kc;
        asm_[i] = r * LDAB + kc * 2;
    }
    uint32_t woffg[4], wsm[4];
#pragma unroll
    for (int j = 0; j < 4; j++) {
        int idx = tid + 256 * j;
        int limb = idx >> 9, rem = idx & 511;
        int n = rem >> 2, kq = (rem & 3) * 8;
        woffg[j] = (uint32_t)limb * DD * EE + (uint32_t)n * EE + kbase + kq;
        wsm[j] = limb * AB + n * LDAB + kq * 2;
    }

    uint32_t aoff[2], boff[4];
#pragma unroll
    for (int mt = 0; mt < 2; mt++)
        aoff[mt] = (row0 + mt * 16 + (lane & 15)) * LDAB + (lane >> 4) * 16;
#pragma unroll
    for (int np = 0; np < 4; np++) {
        int nl = n0 + np * 16 + (lane & 7) + ((lane >> 4) & 1) * 8;
        boff[np] = nl * LDAB + (lane & 8) * 2;
    }

    float c[2][8][4];
#pragma unroll
    for (int mt = 0; mt < 2; mt++)
#pragma unroll
        for (int nt = 0; nt < 8; nt++)
#pragma unroll
            for (int u = 0; u < 4; u++) c[mt][nt][u] = 0.f;

    float4 av[4];
    uint4 wv[4];
#pragma unroll
    for (int i = 0; i < 4; i++) av[i] = *(const float4*)(A + aoffg[i]);
#pragma unroll
    for (int j = 0; j < 4; j++) wv[j] = *(const uint4*)(wt + woffg[j]);

    {
        const uint32_t abase = sb, wbase = sb + S_W;
#pragma unroll
        for (int i = 0; i < 4; i++) {
            __nv_bfloat162 h0 = __float22bfloat162_rn(make_float2(av[i].x, av[i].y));
            __nv_bfloat162 h1 = __float22bfloat162_rn(make_float2(av[i].z, av[i].w));
            float2 hf0 = __bfloat1622float2(h0), hf1 = __bfloat1622float2(h1);
            __nv_bfloat162 m0 = __float22bfloat162_rn(
                make_float2(av[i].x - hf0.x, av[i].y - hf0.y));
            __nv_bfloat162 m1 = __float22bfloat162_rn(
                make_float2(av[i].z - hf1.x, av[i].w - hf1.y));
            sts64(abase + asm_[i], pack_bf16x2(h0), pack_bf16x2(h1));
            sts64(abase + AB + asm_[i], pack_bf16x2(m0), pack_bf16x2(m1));
        }
#pragma unroll
        for (int j = 0; j < 4; j++) sts128(wbase + wsm[j], wv[j]);
    }
    __syncthreads();

    for (int it = 0; it < nch; ++it) {
        const int buf = it & 1;
        if (it + 1 < nch) {
            const int kb = (it + 1) * BK;
#pragma unroll
            for (int i = 0; i < 4; i++) av[i] = *(const float4*)(A + aoffg[i] + kb);
#pragma unroll
            for (int j = 0; j < 4; j++) wv[j] = *(const uint4*)(wt + woffg[j] + kb);
        }

        const uint32_t aH = sb + buf * 2 * AB;
        const uint32_t aM = aH + AB;
        const uint32_t wH = sb + S_W + buf * 2 * AB;
        const uint32_t wM = wH + AB;
#pragma unroll
        for (int kk = 0; kk < 2; kk++) {
            uint32_t ah[2][4], am[2][4], bh[4][4], bm[4][4];
#pragma unroll
            for (int mt = 0; mt < 2; mt++) {
                ldsm4(ah[mt], aH + aoff[mt] + kk * 32);
                ldsm4(am[mt], aM + aoff[mt] + kk * 32);
            }
#pragma unroll
            for (int np = 0; np < 4; np++) {
                ldsm4(bh[np], wH + boff[np] + kk * 32);
                ldsm4(bm[np], wM + boff[np] + kk * 32);
            }
#pragma unroll
            for (int mt = 0; mt < 2; mt++)
#pragma unroll
                for (int nt = 0; nt < 8; nt++) {
                    const uint32_t* BH = &bh[nt >> 1][(nt & 1) * 2];
                    const uint32_t* BM = &bm[nt >> 1][(nt & 1) * 2];
                    mma16816(c[mt][nt], ah[mt], BH);
                    mma16816(c[mt][nt], ah[mt], BM);
                    mma16816(c[mt][nt], am[mt], BH);
                }
        }

        if (it + 1 < nch) {
            __syncthreads();
            const uint32_t abase = sb + ((it + 1) & 1) * 2 * AB;
            const uint32_t wbase = sb + S_W + ((it + 1) & 1) * 2 * AB;
#pragma unroll
            for (int i = 0; i < 4; i++) {
                __nv_bfloat162 h0 =
                    __float22bfloat162_rn(make_float2(av[i].x, av[i].y));
                __nv_bfloat162 h1 =
                    __float22bfloat162_rn(make_float2(av[i].z, av[i].w));
                float2 hf0 = __bfloat1622float2(h0), hf1 = __bfloat1622float2(h1);
                __nv_bfloat162 m0 = __float22bfloat162_rn(
                    make_float2(av[i].x - hf0.x, av[i].y - hf0.y));
                __nv_bfloat162 m1 = __float22bfloat162_rn(
                    make_float2(av[i].z - hf1.x, av[i].w - hf1.y));
                sts64(abase + asm_[i], pack_bf16x2(h0), pack_bf16x2(h1));
                sts64(abase + AB + asm_[i], pack_bf16x2(m0), pack_bf16x2(m1));
            }
#pragma unroll
            for (int j = 0; j < 4; j++) sts128(wbase + wsm[j], wv[j]);
            __syncthreads();
        }
    }

    // -------- epilogue --------
    if (!GATHER) {
#pragma unroll
        for (int mt = 0; mt < 2; mt++) {
            float slo = 0.f, shi = 0.f;
#pragma unroll
            for (int nt = 0; nt < 8; nt++) {
                slo += c[mt][nt][0] * c[mt][nt][0] + c[mt][nt][1] * c[mt][nt][1];
                shi += c[mt][nt][2] * c[mt][nt][2] + c[mt][nt][3] * c[mt][nt][3];
            }
            slo += __shfl_xor_sync(0xffffffffu, slo, 1);
            slo += __shfl_xor_sync(0xffffffffu, slo, 2);
            shi += __shfl_xor_sync(0xffffffffu, shi, 1);
            shi += __shfl_xor_sync(0xffffffffu, shi, 2);
            if ((lane & 3) == 0) {
                int rl = row0 + mt * 16 + (lane >> 2);
                npart[wc][rl] = slo;
                npart[wc][rl + 8] = shi;
            }
        }
        __syncthreads();
        if (tid < 128)
            g_norm[tile * 128 + tid] = npart[0][tid] + npart[1][tid];
    }

#pragma unroll
    for (int mt = 0; mt < 2; mt++) {
        int rl = row0 + mt * 16 + (lane >> 2);
#pragma unroll
        for (int nt = 0; nt < 8; nt++) {
            int col = n0 + nt * 8 + (lane & 3) * 2;
            if (!GATHER) {
                float* p0 = g_q + (size_t)(tile * 128 + rl) * DD + col;
                *(float2*)p0 = make_float2(c[mt][nt][0], c[mt][nt][1]);
                *(float2*)(p0 + 8 * DD) = make_float2(c[mt][nt][2], c[mt][nt][3]);
            } else {
                int r0g = tile * 128 + rl;
                if (r0g < KTOP) {
                    float* p0 = part + ((size_t)b * KTOP + r0g) * DD + col;
                    *(float2*)p0 = make_float2(c[mt][nt][0], c[mt][nt][1]);
                }
                if (r0g + 8 < KTOP) {
                    float* p1 = part + ((size_t)b * KTOP + r0g + 8) * DD + col;
                    *(float2*)p1 = make_float2(c[mt][nt][2], c[mt][nt][3]);
                }
            }
        }
    }
}

// ---------------- split-K reduction for k/v ----------------
__global__ void reduce_kv() {
    const int n = BB * KTOP * DD;
    for (int idx = blockIdx.x * blockDim.x + threadIdx.x; idx < 2 * n;
         idx += gridDim.x * blockDim.x) {
        int mat = (idx >= n) ? 1 : 0;
        int off = mat ? idx - n : idx;
        float s = 0.f;
#pragma unroll
        for (int z = 0; z < NKV; z++)
            s += g_part[(size_t)(z * 2 + mat) * n + off];
        (mat ? g_vtop : g_ktop)[off] = s;
    }
}

// ---------------- set-based top-k: binary search on norm bits ----------------
// Output order is arbitrary-but-deterministic; attention output is invariant
// to the ordering of the selected set.
__global__ __launch_bounds__(1024) void topk_select() {
    const int b = blockIdx.x, tid = threadIdx.x;
    const int lane = tid & 31, w = tid >> 5;
    __shared__ int wsum[32];
    __shared__ int s_tot;
    __shared__ int s_cand;

    uint32_t bits[4];
#pragma unroll
    for (int i = 0; i < 4; i++)
        bits[i] = __float_as_uint(g_norm[b * TT + tid + i * 1024]);
    if (tid == 0) s_cand = 0;

    // binary search: thr = 409th-largest bits value
    uint32_t lo = 0, hi = 0xFFFFFFFFu;
    for (int step = 0; step < 32; ++step) {
        uint32_t mid = lo + ((hi - lo) >> 1);
        int cctr = (bits[0] >= mid) + (bits[1] >= mid) + (bits[2] >= mid) +
                   (bits[3] >= mid);
#pragma unroll
        for (int o = 16; o; o >>= 1) cctr += __shfl_xor_sync(0xffffffffu, cctr, o);
        if (lane == 0) wsum[w] = cctr;
        __syncthreads();
        if (tid < 32) {
            int s = wsum[tid];
#pragma unroll
            for (int o = 16; o; o >>= 1) s += __shfl_xor_sync(0xffffffffu, s, o);
            if (tid == 0) s_tot = s;
        }
        __syncthreads();
        if (s_tot >= KTOP) lo = mid; else hi = mid;
        __syncthreads();
    }
    const float thrv = __uint_as_float(lo);
    const uint32_t bhi = __float_as_uint(thrv * (1.f + 4e-5f));
    const uint32_t blo = __float_as_uint(thrv * (1.f - 4e-5f));

    // sure rows (> bhi): deterministic compaction via prefix scan
    int f[4], myc = 0;
#pragma unroll
    for (int i = 0; i < 4; i++) {
        f[i] = (bits[i] > bhi);
        myc += f[i];
    }
    int incl = myc;
#pragma unroll
    for (int o = 1; o < 32; o <<= 1) {
        int nvv = __shfl_up_sync(0xffffffffu, incl, o);
        if (lane >= o) incl += nvv;
    }
    if (lane == 31) wsum[w] = incl;
    __syncthreads();
    if (tid < 32) {
        int v2 = wsum[tid];
        int inc2 = v2;
#pragma unroll
        for (int o = 1; o < 32; o <<= 1) {
            int nvv = __shfl_up_sync(0xffffffffu, inc2, o);
            if (tid >= o) inc2 += nvv;
        }
        wsum[tid] = inc2 - v2;
        if (tid == 31) s_tot = inc2;
    }
    __syncthreads();
    int pos = wsum[w] + (incl - myc);
#pragma unroll
    for (int i = 0; i < 4; i++) {
        if (f[i]) g_topidx[b * KTOP + pos++] = tid + i * 1024;
    }
    if (tid == 0) g_nsel[b] = s_tot;

    // candidates in [blo, bhi]
#pragma unroll
    for (int i = 0; i < 4; i++) {
        if (bits[i] >= blo && bits[i] <= bhi) {
            int slot = atomicAdd(&s_cand, 1);
            if (slot < NCAND) g_band[b][slot] = tid + i * 1024;
        }
    }
    __syncthreads();
    if (tid == 0) g_ncand[b] = (s_cand < NCAND) ? s_cand : NCAND;
}

// ---------------- exact fp32 norms for candidate rows ----------------
__global__ __launch_bounds__(256) void refine_kernel(const float* __restrict__ A,
                                                     const float* __restrict__ Wq) {
    const int slot = blockIdx.x, b = blockIdx.y;
    if (slot >= g_ncand[b]) return;
    const int n = threadIdx.x & 127, half = threadIdx.x >> 7;
    const int row = g_band[b][slot];
    const float* x = A + ((size_t)b * TT + row) * EE + half * (EE / 2);
    const float* wp = Wq + (size_t)half * (EE / 2) * DD + n;
    float s0 = 0.f, s1 = 0.f, s2 = 0.f, s3 = 0.f;
#pragma unroll 2
    for (int k = 0; k < EE / 2; k += 4) {
        s0 += x[k] * wp[(size_t)k * DD];
        s1 += x[k + 1] * wp[(size_t)(k + 1) * DD];
        s2 += x[k + 2] * wp[(size_t)(k + 2) * DD];
        s3 += x[k + 3] * wp[(size_t)(k + 3) * DD];
    }
    __shared__ float qv[2][128];
    qv[half][n] = (s0 + s1) + (s2 + s3);
    __syncthreads();
    __shared__ float red[128];
    if (threadIdx.x < 128) {
        float q = qv[0][n] + qv[1][n];
        red[n] = q * q;
    }
    __syncthreads();
    for (int o = 64; o > 0; o >>= 1) {
        if (threadIdx.x < o) red[threadIdx.x] += red[threadIdx.x + o];
        __syncthreads();
    }
    if (threadIdx.x == 0) g_bnorm[b][slot] = red[0];
}

// ---------------- finalize: rank candidates exactly, gather q_top ----------
__global__ __launch_bounds__(1024) void finalize_kernel() {
    const int b = blockIdx.x, tid = threadIdx.x;
    __shared__ int sidx[KTOP];
    __shared__ unsigned long long bkey[NCAND];
    const int C1 = g_nsel[b];
    const int nc = g_ncand[b];
    const int remaining = KTOP - C1;
    if (tid < nc) {
        int r = g_band[b][tid];
        unsigned nb = __float_as_uint(g_bnorm[b][tid]);
        bkey[tid] = ((unsigned long long)nb << 32) | (unsigned)(0xFFFFFFFFu - r);
    }
    __syncthreads();
    if (tid < nc) {
        unsigned long long me = bkey[tid];
        int rank = 0;
        for (int t = 0; t < nc; t++) rank += (bkey[t] > me);
        if (rank < remaining) {
            int r = (int)(0xFFFFFFFFu - (unsigned)(me & 0xFFFFFFFFull));
            g_topidx[b * KTOP + C1 + rank] = r;
            sidx[C1 + rank] = r;
        }
    }
    for (int t = tid; t < C1; t += 1024) sidx[t] = g_topidx[b * KTOP + t];
    __syncthreads();
    for (int u = tid; u < KTOP * DD; u += 1024) {
        int r = u >> 7, d = u & 127;
        g_qtop[((size_t)b * KTOP + r) * DD + d] =
            g_q[((size_t)b * TT + sidx[r]) * DD + d];
    }
}

// ---------------- attention on the top-k set, scattered store ----------------
__global__ __launch_bounds__(256) void attn_kernel(float* __restrict__ out) {
    constexpr int QT = 16;
    constexpr int NT = 26;
    constexpr int CW = 416;
    __shared__ float q_s[QT][132];
    __shared__ float kv_s[QT][132];
    __shared__ float S_s[QT][CW];

    const int b = blockIdx.x / NT;
    const int qt = blockIdx.x % NT;
    const int q0 = qt * QT;
    const int tid = threadIdx.x;
    const float scale = 0.08838834764831845f;

    for (int u = tid; u < QT * DD; u += 256) {
        int i = u >> 7, d = u & 127;
        int r = q0 + i;
        q_s[i][d] = (r < KTOP) ? g_qtop[((size_t)b * KTOP + r) * DD + d] : 0.f;
    }

    const int i = tid >> 4;
    const int jj = tid & 15;

    for (int jt = 0; jt < NT; jt++) {
        __syncthreads();
        for (int u = tid; u < QT * DD; u += 256) {
            int j2 = u >> 7, d = u & 127;
            int j = jt * QT + j2;
            kv_s[j2][d] = (j < KTOP) ? g_ktop[((size_t)b * KTOP + j) * DD + d] : 0.f;
        }
        __syncthreads();
        float s = 0.f;
#pragma unroll
        for (int d4 = 0; d4 < DD; d4 += 4) {
            float4 qa = *(const float4*)&q_s[i][d4];
            float4 kb = *(const float4*)&kv_s[jj][d4];
            s += qa.x * kb.x + qa.y * kb.y + qa.z * kb.z + qa.w * kb.w;
        }
        int j = jt * QT + jj;
        S_s[i][j] = (j < KTOP) ? s * scale : -1e30f;
    }
    __syncthreads();

    {
        int l = tid & 15;
        float m = -1e30f;
        for (int cc = l; cc < CW; cc += 16) m = fmaxf(m, S_s[i][cc]);
#pragma unroll
        for (int o = 8; o; o >>= 1) m = fmaxf(m, __shfl_xor_sync(0xffffffffu, m, o));
        float sum = 0.f;
        for (int cc = l; cc < CW; cc += 16) {
            float e = __expf(S_s[i][cc] - m);
            S_s[i][cc] = e;
            sum += e;
        }
#pragma unroll
        for (int o = 8; o; o >>= 1) sum += __shfl_xor_sync(0xffffffffu, sum, o);
        float inv = 1.f / sum;
        for (int cc = l; cc < CW; cc += 16) S_s[i][cc] *= inv;
    }

    float acc[8] = {0.f, 0.f, 0.f, 0.f, 0.f, 0.f, 0.f, 0.f};
    const int d0 = (tid & 15) * 8;
    for (int jt = 0; jt < NT; jt++) {
        __syncthreads();
        for (int u = tid; u < QT * DD; u += 256) {
            int j2 = u >> 7, d = u & 127;
            int j = jt * QT + j2;
            kv_s[j2][d] = (j < KTOP) ? g_vtop[((size_t)b * KTOP + j) * DD + d] : 0.f;
        }
        __syncthreads();
#pragma unroll
        for (int j2 = 0; j2 < QT; j2++) {
            float p = S_s[i][jt * QT + j2];
            float4 v0 = *(const float4*)&kv_s[j2][d0];
            float4 v1 = *(const float4*)&kv_s[j2][d0 + 4];
            acc[0] += p * v0.x;
            acc[1] += p * v0.y;
            acc[2] += p * v0.z;
            acc[3] += p * v0.w;
            acc[4] += p * v1.x;
            acc[5] += p * v1.y;
            acc[6] += p * v1.z;
            acc[7] += p * v1.w;
        }
    }
    int r = q0 + i;
    if (r < KTOP) {
        int rg = g_topidx[b * KTOP + r];
        float* op = out + ((size_t)b * TT + rg) * DD + d0;
        *(float4*)op = make_float4(acc[0], acc[1], acc[2], acc[3]);
        *(float4*)(op + 4) = make_float4(acc[4], acc[5], acc[6], acc[7]);
    }
}

// ---------------- launch ----------------
extern "C" void kernel_launch(void* const* d_in, const int* in_sizes, int n_in,
                              void* d_out, int out_size) {
    (void)in_sizes;
    (void)n_in;
    (void)out_size;
    const float* index = (const float*)d_in[0];
    const float* Wq = (const float*)d_in[1];
    const float* Wk = (const float*)d_in[2];
    const float* Wv = (const float*)d_in[3];
    float* out = (float*)d_out;

    cudaFuncSetAttribute(gemm_mma<false>,
                         cudaFuncAttributeMaxDynamicSharedMemorySize, S_TOTAL);
    cudaFuncSetAttribute(gemm_mma<true>,
                         cudaFuncAttributeMaxDynamicSharedMemorySize, S_TOTAL);

    zero_kernel<<<512, 256>>>((float4*)out, BB * TT * DD / 4);          // 1
    wprep_kernel<<<dim3(EE / 32, DD / 32), 256>>>(Wq, Wk, Wv);          // 2
    init_sel<<<1, 32>>>();                                              // 3
    gemm_mma<false><<<(BB * TT) / 128, 256, S_TOTAL>>>(index);          // 4 (profiled)
    topk_select<<<BB, 1024>>>();                                        // 5
    refine_kernel<<<dim3(NCAND, BB), 256>>>(index, Wq);                 // 6
    finalize_kernel<<<BB, 1024>>>();                                    // 7
    gemm_mma<true><<<dim3(16, 2, NKV), 256, S_TOTAL>>>(index);          // 8
    reduce_kv<<<512, 256>>>();                                          // 9
    attn_kernel<<<BB * 26, 256>>>(out);                                 // 10
}

// round 9
// speedup vs baseline: 1.6987x; 1.5095x over previous
#include <cuda_runtime.h>
#include <cuda_bf16.h>
#include <cstdint>

#define BB 4
#define TT 4096
#define EE 2048
#define DD 128
#define KTOP 409
#define NCAND 32
#define NKV 4   // split-K slices for gather GEMM

// ---------------- scratch (device globals) ----------------
__device__ float g_q[(size_t)BB * TT * DD];
__device__ float g_norm[BB * TT];
__device__ int   g_topidx[BB * KTOP];
__device__ int   g_nsel[BB];
__device__ int   g_ncand[BB];
__device__ int   g_band[BB][NCAND];
__device__ float g_bnorm[BB][NCAND];
__device__ float g_qtop[BB * KTOP * DD];
__device__ float g_ktop[BB * KTOP * DD];
__device__ float g_vtop[BB * KTOP * DD];
__device__ float g_part[(size_t)NKV * 2 * BB * KTOP * DD];
// W transposed + split into 2 bf16 limbs: [mat][limb][n(128)][k(2048)]
__device__ __nv_bfloat16 g_wt[3][2][DD][EE];

// ---------------- helpers ----------------
__device__ __forceinline__ uint32_t smem_u32(const void* p) {
    uint32_t a;
    asm("{ .reg .u64 t; cvta.to.shared.u64 t, %1; cvt.u32.u64 %0, t; }"
        : "=r"(a) : "l"(p));
    return a;
}
__device__ __forceinline__ void ldsm4(uint32_t* r, uint32_t addr) {
    asm volatile("ldmatrix.sync.aligned.m8n8.x4.shared.b16 {%0,%1,%2,%3}, [%4];"
                 : "=r"(r[0]), "=r"(r[1]), "=r"(r[2]), "=r"(r[3]) : "r"(addr));
}
__device__ __forceinline__ void mma16816(float* c, const uint32_t* a,
                                         const uint32_t* b) {
    asm volatile(
        "mma.sync.aligned.m16n8k16.row.col.f32.bf16.bf16.f32 "
        "{%0,%1,%2,%3}, {%4,%5,%6,%7}, {%8,%9}, {%0,%1,%2,%3};"
        : "+f"(c[0]), "+f"(c[1]), "+f"(c[2]), "+f"(c[3])
        : "r"(a[0]), "r"(a[1]), "r"(a[2]), "r"(a[3]), "r"(b[0]), "r"(b[1]));
}
__device__ __forceinline__ void sts64(uint32_t a, uint32_t lo, uint32_t hi) {
    asm volatile("st.shared.v2.b32 [%0], {%1,%2};" :: "r"(a), "r"(lo), "r"(hi));
}
__device__ __forceinline__ uint32_t pack_bf16x2(__nv_bfloat162 v) {
    return *reinterpret_cast<uint32_t*>(&v);
}
__device__ __forceinline__ void cp_async16(uint32_t dst, const void* src) {
    asm volatile("cp.async.cg.shared.global [%0], [%1], 16;"
                 :: "r"(dst), "l"(src));
}
__device__ __forceinline__ void cp_commit() {
    asm volatile("cp.async.commit_group;" ::: "memory");
}
__device__ __forceinline__ void cp_wait0() {
    asm volatile("cp.async.wait_group 0;" ::: "memory");
}
__device__ __forceinline__ void bar_sync(int id) {
    asm volatile("bar.sync %0, 512;" :: "r"(id) : "memory");
}
__device__ __forceinline__ void bar_arrive(int id) {
    asm volatile("bar.arrive %0, 512;" :: "r"(id) : "memory");
}

// ---------------- geometry ----------------
constexpr int BK = 32;
constexpr int NCH = EE / BK;      // 64 chunks (full depth)
constexpr int LDAB = 80;          // smem row stride bytes (conflict-free ldmatrix)
constexpr int AB = 128 * LDAB;    // 10240 bytes per limb buffer
constexpr int NSTG = 4;           // pipeline stages
constexpr uint32_t STAGE = 4 * AB;        // Ah, Am, Wh, Wm per stage = 40960
constexpr uint32_t S_TOTAL = NSTG * STAGE;  // 163840
// barrier ids
#define B_FULL 1
#define B_EMPTY 5

// ---------------- zero output ----------------
__global__ void zero_kernel(float4* o, int n4) {
    for (int i = blockIdx.x * blockDim.x + threadIdx.x; i < n4;
         i += gridDim.x * blockDim.x)
        o[i] = make_float4(0.f, 0.f, 0.f, 0.f);
}

// ---------------- W prep: transpose + 2-limb bf16 split ----------------
__global__ void wprep_kernel(const float* __restrict__ Wq,
                             const float* __restrict__ Wk,
                             const float* __restrict__ Wv) {
    __shared__ float t[32][33];
    const int tid = threadIdx.x;
    const int bk = blockIdx.x * 32, bn = blockIdx.y * 32;
    const float* Ws[3] = {Wq, Wk, Wv};
    for (int m = 0; m < 3; m++) {
        const float* W = Ws[m];
#pragma unroll
        for (int p = 0; p < 4; p++) {
            int i = p * 8 + (tid >> 5), j = tid & 31;
            t[i][j] = W[(bk + i) * DD + bn + j];
        }
        __syncthreads();
#pragma unroll
        for (int p = 0; p < 4; p++) {
            int j = p * 8 + (tid >> 5), i = tid & 31;
            float x = t[i][j];
            __nv_bfloat16 h = __float2bfloat16_rn(x);
            float r1 = x - __bfloat162float(h);
            __nv_bfloat16 md = __float2bfloat16_rn(r1);
            int n = bn + j, k = bk + i;
            g_wt[m][0][n][k] = h;
            g_wt[m][1][n][k] = md;
        }
        __syncthreads();
    }
}

// ---------------- tiny init (keeps gemm at launch #4 for profiling) --------
__global__ void init_sel() {
    if (threadIdx.x < BB) {
        g_nsel[threadIdx.x] = 0;
        g_ncand[threadIdx.x] = 0;
    }
}

// ---------------- warp-specialized mma.sync split-bf16 GEMM ----------------
// 512 threads: warps 0-7 consumers (ldsm+mma), warps 8-15 producers
// (cp.async W limbs, load+convert A to 2 bf16 limbs, STS). 4-stage ring.
// !GATHER: grid=128 tiles, full depth -> g_q + g_norm.
// GATHER : grid=(16, 2, NKV) split-K -> g_part slices.
template <bool GATHER>
__global__ __launch_bounds__(512, 1) void gemm_mma(const float* __restrict__ A) {
    extern __shared__ char smem[];
    __shared__ float npart[2][128];
    const uint32_t sb = smem_u32(smem);
    const int tid = threadIdx.x, wid = tid >> 5, lane = tid & 31;
    const bool isProd = (tid >= 256);
    const int ptid = tid & 255;

    int b = 0, tile, mat = 0, kbase = 0, nch = NCH;
    const __nv_bfloat16* wt;
    float* part = nullptr;
    if (GATHER) {
        b = blockIdx.x >> 2;
        tile = blockIdx.x & 3;
        mat = blockIdx.y;
        kbase = blockIdx.z * (EE / NKV);
        nch = (EE / NKV) / BK;   // 16
        wt = &g_wt[1 + mat][0][0][0];
        part = g_part + (size_t)(blockIdx.z * 2 + mat) * (BB * KTOP * DD);
    } else {
        tile = blockIdx.x;
        wt = &g_wt[0][0][0][0];
    }

    if (isProd) {
        // ================= PRODUCER =================
        uint32_t aoffg[4], asm_[4];
#pragma unroll
        for (int i = 0; i < 4; i++) {
            int idx = ptid + 256 * i;
            int r = idx >> 3, kc = (idx & 7) * 4;
            int gr;
            if (GATHER) {
                int rl = tile * 128 + r;
                if (rl >= KTOP) rl = KTOP - 1;
                gr = b * TT + g_topidx[b * KTOP + rl];
            } else {
                gr = tile * 128 + r;
            }
            aoffg[i] = (uint32_t)gr * EE + kbase + kc;
            asm_[i] = r * LDAB + kc * 2;
        }
        uint32_t woffg[4], wsm[4];
#pragma unroll
        for (int j = 0; j < 4; j++) {
            int idx = ptid + 256 * j;
            int limb = idx >> 9, rem = idx & 511;
            int n = rem >> 2, kq = (rem & 3) * 8;
            woffg[j] = (uint32_t)limb * DD * EE + (uint32_t)n * EE + kbase + kq;
            wsm[j] = 2 * AB + limb * AB + n * LDAB + kq * 2;
        }

        float4 av[4];
#pragma unroll
        for (int i = 0; i < 4; i++) av[i] = *(const float4*)(A + aoffg[i]);

        for (int it = 0; it < nch; ++it) {
            const int s = it & (NSTG - 1);
            const uint32_t base = sb + s * STAGE;
            bar_sync(B_EMPTY + s);
            // W limbs straight gmem->smem
            const int kb = it * BK;
#pragma unroll
            for (int j = 0; j < 4; j++)
                cp_async16(base + wsm[j], wt + woffg[j] + kb);
            cp_commit();
            // A: convert fp32 -> h/m limbs, STS
#pragma unroll
            for (int i = 0; i < 4; i++) {
                __nv_bfloat162 h0 =
                    __float22bfloat162_rn(make_float2(av[i].x, av[i].y));
                __nv_bfloat162 h1 =
                    __float22bfloat162_rn(make_float2(av[i].z, av[i].w));
                float2 hf0 = __bfloat1622float2(h0), hf1 = __bfloat1622float2(h1);
                __nv_bfloat162 m0 = __float22bfloat162_rn(
                    make_float2(av[i].x - hf0.x, av[i].y - hf0.y));
                __nv_bfloat162 m1 = __float22bfloat162_rn(
                    make_float2(av[i].z - hf1.x, av[i].w - hf1.y));
                sts64(base + asm_[i], pack_bf16x2(h0), pack_bf16x2(h1));
                sts64(base + AB + asm_[i], pack_bf16x2(m0), pack_bf16x2(m1));
            }
            // prefetch next A chunk
            if (it + 1 < nch) {
                const int kn = (it + 1) * BK;
#pragma unroll
                for (int i = 0; i < 4; i++)
                    av[i] = *(const float4*)(A + aoffg[i] + kn);
            }
            cp_wait0();
            __threadfence_block();
            bar_arrive(B_FULL + s);
        }
    } else {
        // ================= CONSUMER =================
        const int wr = wid >> 1, wc = wid & 1;
        const int row0 = wr * 32, n0 = wc * 64;
        uint32_t aoff[2], boff[4];
#pragma unroll
        for (int mt = 0; mt < 2; mt++)
            aoff[mt] = (row0 + mt * 16 + (lane & 15)) * LDAB + (lane >> 4) * 16;
#pragma unroll
        for (int np = 0; np < 4; np++) {
            int nl = n0 + np * 16 + (lane & 7) + ((lane >> 4) & 1) * 8;
            boff[np] = nl * LDAB + (lane & 8) * 2;
        }

        float c[2][8][4];
#pragma unroll
        for (int mt = 0; mt < 2; mt++)
#pragma unroll
            for (int nt = 0; nt < 8; nt++)
#pragma unroll
                for (int u = 0; u < 4; u++) c[mt][nt][u] = 0.f;

#pragma unroll
        for (int s = 0; s < NSTG; s++) bar_arrive(B_EMPTY + s);

        for (int it = 0; it < nch; ++it) {
            const int s = it & (NSTG - 1);
            const uint32_t base = sb + s * STAGE;
            bar_sync(B_FULL + s);
#pragma unroll
            for (int kk = 0; kk < 2; kk++) {
                uint32_t ah[2][4], am[2][4];
#pragma unroll
                for (int mt = 0; mt < 2; mt++) {
                    ldsm4(ah[mt], base + aoff[mt] + kk * 32);
                    ldsm4(am[mt], base + AB + aoff[mt] + kk * 32);
                }
#pragma unroll
                for (int np = 0; np < 4; np++) {
                    uint32_t bh[4], bm[4];
                    ldsm4(bh, base + 2 * AB + boff[np] + kk * 32);
                    ldsm4(bm, base + 3 * AB + boff[np] + kk * 32);
#pragma unroll
                    for (int mt = 0; mt < 2; mt++) {
                        mma16816(c[mt][2 * np], ah[mt], bh);
                        mma16816(c[mt][2 * np], ah[mt], bm);
                        mma16816(c[mt][2 * np], am[mt], bh);
                        mma16816(c[mt][2 * np + 1], ah[mt], bh + 2);
                        mma16816(c[mt][2 * np + 1], ah[mt], bm + 2);
                        mma16816(c[mt][2 * np + 1], am[mt], bh + 2);
                    }
                }
            }
            bar_arrive(B_EMPTY + s);
        }

        // -------- epilogue (consumers hold C) --------
        if (!GATHER) {
#pragma unroll
            for (int mt = 0; mt < 2; mt++) {
                float slo = 0.f, shi = 0.f;
#pragma unroll
                for (int nt = 0; nt < 8; nt++) {
                    slo += c[mt][nt][0] * c[mt][nt][0] +
                           c[mt][nt][1] * c[mt][nt][1];
                    shi += c[mt][nt][2] * c[mt][nt][2] +
                           c[mt][nt][3] * c[mt][nt][3];
                }
                slo += __shfl_xor_sync(0xffffffffu, slo, 1);
                slo += __shfl_xor_sync(0xffffffffu, slo, 2);
                shi += __shfl_xor_sync(0xffffffffu, shi, 1);
                shi += __shfl_xor_sync(0xffffffffu, shi, 2);
                if ((lane & 3) == 0) {
                    int rl = row0 + mt * 16 + (lane >> 2);
                    npart[wc][rl] = slo;
                    npart[wc][rl + 8] = shi;
                }
            }
        }

#pragma unroll
        for (int mt = 0; mt < 2; mt++) {
            int rl = row0 + mt * 16 + (lane >> 2);
#pragma unroll
            for (int nt = 0; nt < 8; nt++) {
                int col = n0 + nt * 8 + (lane & 3) * 2;
                if (!GATHER) {
                    float* p0 = g_q + (size_t)(tile * 128 + rl) * DD + col;
                    *(float2*)p0 = make_float2(c[mt][nt][0], c[mt][nt][1]);
                    *(float2*)(p0 + 8 * DD) =
                        make_float2(c[mt][nt][2], c[mt][nt][3]);
                } else {
                    int r0g = tile * 128 + rl;
                    if (r0g < KTOP) {
                        float* p0 = part + ((size_t)b * KTOP + r0g) * DD + col;
                        *(float2*)p0 = make_float2(c[mt][nt][0], c[mt][nt][1]);
                    }
                    if (r0g + 8 < KTOP) {
                        float* p1 =
                            part + ((size_t)b * KTOP + r0g + 8) * DD + col;
                        *(float2*)p1 = make_float2(c[mt][nt][2], c[mt][nt][3]);
                    }
                }
            }
        }
    }

    if (!GATHER) {
        __syncthreads();   // all 512 threads
        if (tid < 128)
            g_norm[tile * 128 + tid] = npart[0][tid] + npart[1][tid];
    }
}

// ---------------- split-K reduction for k/v ----------------
__global__ void reduce_kv() {
    const int n = BB * KTOP * DD;
    for (int idx = blockIdx.x * blockDim.x + threadIdx.x; idx < 2 * n;
         idx += gridDim.x * blockDim.x) {
        int mat = (idx >= n) ? 1 : 0;
        int off = mat ? idx - n : idx;
        float s = 0.f;
#pragma unroll
        for (int z = 0; z < NKV; z++)
            s += g_part[(size_t)(z * 2 + mat) * n + off];
        (mat ? g_vtop : g_ktop)[off] = s;
    }
}

// ---------------- set-based top-k: binary search on norm bits ----------------
__global__ __launch_bounds__(1024) void topk_select() {
    const int b = blockIdx.x, tid = threadIdx.x;
    const int lane = tid & 31, w = tid >> 5;
    __shared__ int wsum[32];
    __shared__ int s_tot;
    __shared__ int s_cand;

    uint32_t bits[4];
#pragma unroll
    for (int i = 0; i < 4; i++)
        bits[i] = __float_as_uint(g_norm[b * TT + tid + i * 1024]);
    if (tid == 0) s_cand = 0;

    uint32_t lo = 0, hi = 0xFFFFFFFFu;
    for (int step = 0; step < 32; ++step) {
        uint32_t mid = lo + ((hi - lo) >> 1);
        int cctr = (bits[0] >= mid) + (bits[1] >= mid) + (bits[2] >= mid) +
                   (bits[3] >= mid);
#pragma unroll
        for (int o = 16; o; o >>= 1) cctr += __shfl_xor_sync(0xffffffffu, cctr, o);
        if (lane == 0) wsum[w] = cctr;
        __syncthreads();
        if (tid < 32) {
            int s = wsum[tid];
#pragma unroll
            for (int o = 16; o; o >>= 1) s += __shfl_xor_sync(0xffffffffu, s, o);
            if (tid == 0) s_tot = s;
        }
        __syncthreads();
        if (s_tot >= KTOP) lo = mid; else hi = mid;
        __syncthreads();
    }
    const float thrv = __uint_as_float(lo);
    const uint32_t bhi = __float_as_uint(thrv * (1.f + 4e-5f));
    const uint32_t blo = __float_as_uint(thrv * (1.f - 4e-5f));

    int f[4], myc = 0;
#pragma unroll
    for (int i = 0; i < 4; i++) {
        f[i] = (bits[i] > bhi);
        myc += f[i];
    }
    int incl = myc;
#pragma unroll
    for (int o = 1; o < 32; o <<= 1) {
        int nvv = __shfl_up_sync(0xffffffffu, incl, o);
        if (lane >= o) incl += nvv;
    }
    if (lane == 31) wsum[w] = incl;
    __syncthreads();
    if (tid < 32) {
        int v2 = wsum[tid];
        int inc2 = v2;
#pragma unroll
        for (int o = 1; o < 32; o <<= 1) {
            int nvv = __shfl_up_sync(0xffffffffu, inc2, o);
            if (tid >= o) inc2 += nvv;
        }
        wsum[tid] = inc2 - v2;
        if (tid == 31) s_tot = inc2;
    }
    __syncthreads();
    int pos = wsum[w] + (incl - myc);
#pragma unroll
    for (int i = 0; i < 4; i++) {
        if (f[i]) g_topidx[b * KTOP + pos++] = tid + i * 1024;
    }
    if (tid == 0) g_nsel[b] = s_tot;

#pragma unroll
    for (int i = 0; i < 4; i++) {
        if (bits[i] >= blo && bits[i] <= bhi) {
            int slot = atomicAdd(&s_cand, 1);
            if (slot < NCAND) g_band[b][slot] = tid + i * 1024;
        }
    }
    __syncthreads();
    if (tid == 0) g_ncand[b] = (s_cand < NCAND) ? s_cand : NCAND;
}

// ---------------- exact fp32 norms for candidate rows ----------------
__global__ __launch_bounds__(256) void refine_kernel(const float* __restrict__ A,
                                                     const float* __restrict__ Wq) {
    const int slot = blockIdx.x, b = blockIdx.y;
    if (slot >= g_ncand[b]) return;
    const int n = threadIdx.x & 127, half = threadIdx.x >> 7;
    const int row = g_band[b][slot];
    const float* x = A + ((size_t)b * TT + row) * EE + half * (EE / 2);
    const float* wp = Wq + (size_t)half * (EE / 2) * DD + n;
    float s0 = 0.f, s1 = 0.f, s2 = 0.f, s3 = 0.f;
#pragma unroll 2
    for (int k = 0; k < EE / 2; k += 4) {
        s0 += x[k] * wp[(size_t)k * DD];
        s1 += x[k + 1] * wp[(size_t)(k + 1) * DD];
        s2 += x[k + 2] * wp[(size_t)(k + 2) * DD];
        s3 += x[k + 3] * wp[(size_t)(k + 3) * DD];
    }
    __shared__ float qv[2][128];
    qv[half][n] = (s0 + s1) + (s2 + s3);
    __syncthreads();
    __shared__ float red[128];
    if (threadIdx.x < 128) {
        float q = qv[0][n] + qv[1][n];
        red[n] = q * q;
    }
    __syncthreads();
    for (int o = 64; o > 0; o >>= 1) {
        if (threadIdx.x < o) red[threadIdx.x] += red[threadIdx.x + o];
        __syncthreads();
    }
    if (threadIdx.x == 0) g_bnorm[b][slot] = red[0];
}

// ---------------- finalize: rank candidates exactly, gather q_top ----------
__global__ __launch_bounds__(1024) void finalize_kernel() {
    const int b = blockIdx.x, tid = threadIdx.x;
    __shared__ int sidx[KTOP];
    __shared__ unsigned long long bkey[NCAND];
    const int C1 = g_nsel[b];
    const int nc = g_ncand[b];
    const int remaining = KTOP - C1;
    if (tid < nc) {
        int r = g_band[b][tid];
        unsigned nb = __float_as_uint(g_bnorm[b][tid]);
        bkey[tid] = ((unsigned long long)nb << 32) | (unsigned)(0xFFFFFFFFu - r);
    }
    __syncthreads();
    if (tid < nc) {
        unsigned long long me = bkey[tid];
        int rank = 0;
        for (int t = 0; t < nc; t++) rank += (bkey[t] > me);
        if (rank < remaining) {
            int r = (int)(0xFFFFFFFFu - (unsigned)(me & 0xFFFFFFFFull));
            g_topidx[b * KTOP + C1 + rank] = r;
            sidx[C1 + rank] = r;
        }
    }
    for (int t = tid; t < C1; t += 1024) sidx[t] = g_topidx[b * KTOP + t];
    __syncthreads();
    for (int u = tid; u < KTOP * DD; u += 1024) {
        int r = u >> 7, d = u & 127;
        g_qtop[((size_t)b * KTOP + r) * DD + d] =
            g_q[((size_t)b * TT + sidx[r]) * DD + d];
    }
}

// ---------------- attention on the top-k set, scattered store ----------------
__global__ __launch_bounds__(256) void attn_kernel(float* __restrict__ out) {
    constexpr int QT = 16;
    constexpr int NT = 26;
    constexpr int CW = 416;
    __shared__ float q_s[QT][132];
    __shared__ float kv_s[QT][132];
    __shared__ float S_s[QT][CW];

    const int b = blockIdx.x / NT;
    const int qt = blockIdx.x % NT;
    const int q0 = qt * QT;
    const int tid = threadIdx.x;
    const float scale = 0.08838834764831845f;

    for (int u = tid; u < QT * DD; u += 256) {
        int i = u >> 7, d = u & 127;
        int r = q0 + i;
        q_s[i][d] = (r < KTOP) ? g_qtop[((size_t)b * KTOP + r) * DD + d] : 0.f;
    }

    const int i = tid >> 4;
    const int jj = tid & 15;

    for (int jt = 0; jt < NT; jt++) {
        __syncthreads();
        for (int u = tid; u < QT * DD; u += 256) {
            int j2 = u >> 7, d = u & 127;
            int j = jt * QT + j2;
            kv_s[j2][d] = (j < KTOP) ? g_ktop[((size_t)b * KTOP + j) * DD + d] : 0.f;
        }
        __syncthreads();
        float s = 0.f;
#pragma unroll
        for (int d4 = 0; d4 < DD; d4 += 4) {
            float4 qa = *(const float4*)&q_s[i][d4];
            float4 kb = *(const float4*)&kv_s[jj][d4];
            s += qa.x * kb.x + qa.y * kb.y + qa.z * kb.z + qa.w * kb.w;
        }
        int j = jt * QT + jj;
        S_s[i][j] = (j < KTOP) ? s * scale : -1e30f;
    }
    __syncthreads();

    {
        int l = tid & 15;
        float m = -1e30f;
        for (int cc = l; cc < CW; cc += 16) m = fmaxf(m, S_s[i][cc]);
#pragma unroll
        for (int o = 8; o; o >>= 1) m = fmaxf(m, __shfl_xor_sync(0xffffffffu, m, o));
        float sum = 0.f;
        for (int cc = l; cc < CW; cc += 16) {
            float e = __expf(S_s[i][cc] - m);
            S_s[i][cc] = e;
            sum += e;
        }
#pragma unroll
        for (int o = 8; o; o >>= 1) sum += __shfl_xor_sync(0xffffffffu, sum, o);
        float inv = 1.f / sum;
        for (int cc = l; cc < CW; cc += 16) S_s[i][cc] *= inv;
    }

    float acc[8] = {0.f, 0.f, 0.f, 0.f, 0.f, 0.f, 0.f, 0.f};
    const int d0 = (tid & 15) * 8;
    for (int jt = 0; jt < NT; jt++) {
        __syncthreads();
        for (int u = tid; u < QT * DD; u += 256) {
            int j2 = u >> 7, d = u & 127;
            int j = jt * QT + j2;
            kv_s[j2][d] = (j < KTOP) ? g_vtop[((size_t)b * KTOP + j) * DD + d] : 0.f;
        }
        __syncthreads();
#pragma unroll
        for (int j2 = 0; j2 < QT; j2++) {
            float p = S_s[i][jt * QT + j2];
            float4 v0 = *(const float4*)&kv_s[j2][d0];
            float4 v1 = *(const float4*)&kv_s[j2][d0 + 4];
            acc[0] += p * v0.x;
            acc[1] += p * v0.y;
            acc[2] += p * v0.z;
            acc[3] += p * v0.w;
            acc[4] += p * v1.x;
            acc[5] += p * v1.y;
            acc[6] += p * v1.z;
            acc[7] += p * v1.w;
        }
    }
    int r = q0 + i;
    if (r < KTOP) {
        int rg = g_topidx[b * KTOP + r];
        float* op = out + ((size_t)b * TT + rg) * DD + d0;
        *(float4*)op = make_float4(acc[0], acc[1], acc[2], acc[3]);
        *(float4*)(op + 4) = make_float4(acc[4], acc[5], acc[6], acc[7]);
    }
}

// ---------------- launch ----------------
extern "C" void kernel_launch(void* const* d_in, const int* in_sizes, int n_in,
                              void* d_out, int out_size) {
    (void)in_sizes;
    (void)n_in;
    (void)out_size;
    const float* index = (const float*)d_in[0];
    const float* Wq = (const float*)d_in[1];
    const float* Wk = (const float*)d_in[2];
    const float* Wv = (const float*)d_in[3];
    float* out = (float*)d_out;

    cudaFuncSetAttribute(gemm_mma<false>,
                         cudaFuncAttributeMaxDynamicSharedMemorySize, S_TOTAL);
    cudaFuncSetAttribute(gemm_mma<true>,
                         cudaFuncAttributeMaxDynamicSharedMemorySize, S_TOTAL);

    zero_kernel<<<512, 256>>>((float4*)out, BB * TT * DD / 4);          // 1
    wprep_kernel<<<dim3(EE / 32, DD / 32), 256>>>(Wq, Wk, Wv);          // 2
    init_sel<<<1, 32>>>();                                              // 3
    gemm_mma<false><<<(BB * TT) / 128, 512, S_TOTAL>>>(index);          // 4 (profiled)
    topk_select<<<BB, 1024>>>();                                        // 5
    refine_kernel<<<dim3(NCAND, BB), 256>>>(index, Wq);                 // 6
    finalize_kernel<<<BB, 1024>>>();                                    // 7
    gemm_mma<true><<<dim3(16, 2, NKV), 512, S_TOTAL>>>(index);          // 8
    reduce_kv<<<512, 256>>>();                                          // 9
    attn_kernel<<<BB * 26, 256>>>(out);                                 // 10
}